// round 9
// baseline (speedup 1.0000x reference)
#include <cuda_runtime.h>

#define T_DIM 32
#define C_DIM 512
#define H_DIM 56
#define W_DIM 56
#define EPSF  1e-6f
#define NHG   8                    // h-groups per t
#define HG_SZ 7                    // h per group
#define NBLK  (T_DIM * NHG)        // 256 blocks = one resident wave
#define NTHR  224                  // 14 float4-quads (w) x 16 c-slots

// Packed (lin, sq) pairs.
__device__ float2 g_H[T_DIM * H_DIM];            // H-axis finals (block-owned)
__device__ float2 g_pW2[T_DIM * NHG * W_DIM];    // W partials folded over 7 h (114 KB)
__device__ unsigned int g_ticket;                // zero-init; last block resets

__global__ __launch_bounds__(NTHR)
void fused_kernel(const float* __restrict__ x, float* __restrict__ out)
{
    const int tid = threadIdx.x;
    const int q   = tid % 14;      // float4-quad within the 56-wide row
    const int r0  = tid / 14;      // c slot 0..15 (c = r0 + 16*ci)
    const int t   = blockIdx.x >> 3;
    const int hg  = blockIdx.x & 7;
    const int h0  = hg * HG_SZ;

    // shA: per-(hh,thread) H partials [7*224], later reused as shH[1792]
    // shB: W park buffer [224*4], later reused as shW[1792]
    __shared__ float2 shA[T_DIM * H_DIM];
    __shared__ float2 shB[T_DIM * H_DIM];

    const float4* __restrict__ x4 = (const float4*)x;
    const size_t tbase = (size_t)t * C_DIM * H_DIM * 14;   // float4 units

    float lw0 = 0.f, lw1 = 0.f, lw2 = 0.f, lw3 = 0.f;      // W accums (whole block range)
    float sw0 = 0.f, sw1 = 0.f, sw2 = 0.f, sw3 = 0.f;

    #pragma unroll
    for (int hh = 0; hh < HG_SZ; ++hh) {
        const int h = h0 + hh;
        // c = r0: offset c*56*14 = r0*784
        size_t base = tbase + (size_t)h * 14 + q + (size_t)r0 * 784;

        float linh = 0.f, sqh = 0.f;
        #pragma unroll 8
        for (int ci = 0; ci < 32; ++ci) {                  // c steps of 16 -> 16*784 float4
            float4 v = __ldcs(&x4[base + (size_t)ci * 12544]);
            linh += v.x + v.y + v.z + v.w;
            sqh  += v.x * v.x + v.y * v.y + v.z * v.z + v.w * v.w;
            lw0 += v.x;  sw0 += v.x * v.x;
            lw1 += v.y;  sw1 += v.y * v.y;
            lw2 += v.z;  sw2 += v.z * v.z;
            lw3 += v.w;  sw3 += v.w * v.w;
        }
        shA[hh * NTHR + tid] = make_float2(linh, sqh);
    }
    __syncthreads();

    // ---- H fold: 7 threads each sum 224 shared entries -> g_H ----
    if (tid < HG_SZ) {
        float a = 0.f, b = 0.f;
        for (int j = 0; j < NTHR; ++j) {
            float2 v = shA[tid * NTHR + j];
            a += v.x; b += v.y;
        }
        g_H[t * H_DIM + h0 + tid] = make_float2(a, b);
    }
    // ---- W park (concurrent with H fold; disjoint buffers) ----
    shB[tid * 4 + 0] = make_float2(lw0, sw0);
    shB[tid * 4 + 1] = make_float2(lw1, sw1);
    shB[tid * 4 + 2] = make_float2(lw2, sw2);
    shB[tid * 4 + 3] = make_float2(lw3, sw3);
    __syncthreads();

    // ---- W gather: 56 threads fold the 16 c-slots -> g_pW2 ----
    if (tid < W_DIM) {
        const int qq = tid >> 2;
        const int ii = tid & 3;
        float a = 0.f, b = 0.f;
        #pragma unroll
        for (int r = 0; r < 16; ++r) {
            float2 v = shB[(r * 14 + qq) * 4 + ii];
            a += v.x; b += v.y;
        }
        g_pW2[(t * NHG + hg) * W_DIM + tid] = make_float2(a, b);
    }
    __threadfence();
    __syncthreads();

    // ---- elect last block (deterministic: counter reset every launch) ----
    __shared__ unsigned int s_last;
    if (tid == 0) s_last = atomicAdd(&g_ticket, 1u);
    __syncthreads();
    if (s_last != NBLK - 1) return;
    if (tid == 0) g_ticket = 0;
    __threadfence();
    __syncthreads();

    // ---- stage finals into shared: shB = W (fold 8 hg), shA = H ----
    for (int p = tid; p < T_DIM * W_DIM; p += NTHR) {
        const int tt = p / W_DIM;
        const int w  = p % W_DIM;
        float a = 0.f, b = 0.f;
        #pragma unroll
        for (int g = 0; g < NHG; ++g) {
            float2 v = g_pW2[(tt * NHG + g) * W_DIM + w];
            a += v.x; b += v.y;
        }
        shB[p] = make_float2(a, b);
    }
    for (int p = tid; p < T_DIM * H_DIM; p += NTHR)
        shA[p] = g_H[p];
    __syncthreads();

    // ---- scans: 64 threads = 32 t x 2 axes ----
    __shared__ float shS[64];
    if (tid < 64) {
        const int tt = tid & 31;
        const int ax = tid >> 5;  // 0 = H, 1 = W
        const float2* __restrict__ s = (ax ? shB : shA) + tt * 56;

        const float n_other = (float)(C_DIM) * 56.f;  // 28672
        float total = 0.f;

        float csq = 0.f, clin = 0.f;
        #pragma unroll
        for (int i = 55; i >= 0; --i) {           // suffix slices [i:]
            float2 v = s[i];
            clin += v.x;
            csq  += v.y;
            float n = n_other * (float)(56 - i);
            total += sqrtf(csq + 2.f * EPSF * clin + (EPSF * EPSF) * n) + EPSF;
        }
        csq = 0.f; clin = 0.f;
        #pragma unroll
        for (int i = 0; i < 56; ++i) {            // prefix slices [:j+1]
            float2 v = s[i];
            clin += v.x;
            csq  += v.y;
            float n = n_other * (float)(i + 1);
            total += sqrtf(csq + 2.f * EPSF * clin + (EPSF * EPSF) * n) + EPSF;
        }
        shS[tid] = total;
    }
    __syncthreads();
    if (tid < 32) {
        float v = shS[tid] + shS[tid + 32];
        #pragma unroll
        for (int off = 16; off > 0; off >>= 1)
            v += __shfl_down_sync(0xffffffffu, v, off);
        if (tid == 0) out[0] = v / 128.f;  // / (T=32 * 4 losses)
    }
}

// ---------------------------------------------------------------------------
extern "C" void kernel_launch(void* const* d_in, const int* in_sizes, int n_in,
                              void* d_out, int out_size)
{
    const float* x = (const float*)d_in[0];
    float* out = (float*)d_out;
    (void)in_sizes; (void)n_in; (void)out_size;

    fused_kernel<<<NBLK, NTHR>>>(x, out);
}

// round 10
// speedup vs baseline: 1.0700x; 1.0700x over previous
#include <cuda_runtime.h>

#define T_DIM 32
#define C_DIM 512
#define H_DIM 56
#define W_DIM 56
#define EPSF  1e-6f
#define NPAIR (T_DIM * H_DIM)   // 1792 (t,h) pairs
#define GRID1 (NPAIR / 2)       // 896 blocks, 2 pairs each -> one even wave
#define GRID2 (T_DIM * 2)       // 64 tail blocks: (t, half)

// Packed (lin, sq) pairs.
__device__ float2 g_H[T_DIM * H_DIM];            // H-axis finals
__device__ float2 g_pW[T_DIM * H_DIM * W_DIM];   // W partials per (t,h)
__device__ float2 g_W2[GRID2 * W_DIM];           // W partials folded over 28 h
__device__ unsigned int g_ticket;                // zero-init; last block resets

// ---------------------------------------------------------------------------
// Kernel 1 (unchanged from R8 — proven ~30us): stream the tensor once.
// 896 blocks x 224 threads, 2 (t,h) pairs each, __ldcs evict-first loads.
// ---------------------------------------------------------------------------
__global__ __launch_bounds__(224) void reduce_kernel(const float* __restrict__ x)
{
    const int tid = threadIdx.x;
    const int q   = tid % 14;
    const int r0  = tid / 14;
    const int wid  = tid >> 5;
    const int lane = tid & 31;
    const int stride4 = (H_DIM * W_DIM) / 4;  // 784 float4 per channel

    __shared__ float sbuf[224 * 8];

    #pragma unroll
    for (int pp = 0; pp < 2; ++pp) {
        const int p = blockIdx.x + pp * GRID1;
        const int t = p / H_DIM;
        const int h = p % H_DIM;

        const float4* __restrict__ base =
            (const float4*)(x + ((size_t)t * C_DIM * H_DIM + (size_t)h) * W_DIM);

        float linh = 0.f, sqh = 0.f;
        float lw0 = 0.f, lw1 = 0.f, lw2 = 0.f, lw3 = 0.f;
        float sw0 = 0.f, sw1 = 0.f, sw2 = 0.f, sw3 = 0.f;

        #pragma unroll 4
        for (int c = r0; c < C_DIM; c += 16) {
            float4 v = __ldcs(&base[(size_t)c * stride4 + q]);
            linh += v.x + v.y + v.z + v.w;
            sqh  += v.x * v.x + v.y * v.y + v.z * v.z + v.w * v.w;
            lw0 += v.x;  sw0 += v.x * v.x;
            lw1 += v.y;  sw1 += v.y * v.y;
            lw2 += v.z;  sw2 += v.z * v.z;
            lw3 += v.w;  sw3 += v.w * v.w;
        }

        // H reduction: shfl in warp, thread 0 folds 7 warps
        float a = linh, b = sqh;
        #pragma unroll
        for (int off = 16; off > 0; off >>= 1) {
            a += __shfl_down_sync(0xffffffffu, a, off);
            b += __shfl_down_sync(0xffffffffu, b, off);
        }
        if (lane == 0) { sbuf[wid] = a; sbuf[8 + wid] = b; }
        __syncthreads();
        if (tid == 0) {
            float la = 0.f, lb = 0.f;
            #pragma unroll
            for (int i = 0; i < 7; ++i) { la += sbuf[i]; lb += sbuf[8 + i]; }
            g_H[t * H_DIM + h] = make_float2(la, lb);
        }
        __syncthreads();

        // W partials: park 8 values, 56 threads gather
        float* my = &sbuf[tid * 8];
        my[0] = lw0; my[1] = lw1; my[2] = lw2; my[3] = lw3;
        my[4] = sw0; my[5] = sw1; my[6] = sw2; my[7] = sw3;
        __syncthreads();

        if (tid < W_DIM) {
            const int qq = tid >> 2;
            const int ii = tid & 3;
            float la = 0.f, lb = 0.f;
            #pragma unroll
            for (int r = 0; r < 16; ++r) {
                const float* src = &sbuf[(r * 14 + qq) * 8];
                la += src[ii];
                lb += src[4 + ii];
            }
            g_pW[(t * H_DIM + h) * W_DIM + tid] = make_float2(la, lb);
        }
        __syncthreads();
    }
}

// ---------------------------------------------------------------------------
// Kernel 2: 64 blocks x 256 threads. Block (t, half) folds 28 h-slices of
// g_pW (thread = (w, h-quarter): 7 unrolled loads; shared 4-way fold) into
// g_W2. Ticket-elected last block (deterministic counter reset) stages
// g_W2 + g_H with all 256 threads and runs the scans.
// ---------------------------------------------------------------------------
__global__ __launch_bounds__(256) void tail_kernel(float* __restrict__ out)
{
    const int blk  = blockIdx.x;
    const int tid  = threadIdx.x;
    const int t0   = blk >> 1;
    const int half = blk & 1;

    __shared__ float2 shP[224];

    // ---- fold 28 h for this (t, half): 224 active threads = 56 w x 4 hq ----
    if (tid < 224) {
        const int w  = tid % W_DIM;
        const int hq = tid / W_DIM;        // 0..3, each covers 7 h
        const int hb = half * 28 + hq * 7;
        float a = 0.f, b = 0.f;
        #pragma unroll
        for (int k = 0; k < 7; ++k) {
            float2 v = g_pW[(t0 * H_DIM + hb + k) * W_DIM + w];
            a += v.x; b += v.y;
        }
        shP[tid] = make_float2(a, b);
    }
    __syncthreads();
    if (tid < W_DIM) {
        float2 v0 = shP[tid],        v1 = shP[tid + 56];
        float2 v2 = shP[tid + 112],  v3 = shP[tid + 168];
        g_W2[blk * W_DIM + tid] =
            make_float2(v0.x + v1.x + v2.x + v3.x, v0.y + v1.y + v2.y + v3.y);
    }
    __threadfence();
    __syncthreads();

    // ---- elect last block ----
    __shared__ unsigned int s_last;
    if (tid == 0) s_last = atomicAdd(&g_ticket, 1u);
    __syncthreads();
    if (s_last != GRID2 - 1) return;
    if (tid == 0) g_ticket = 0;          // deterministic across graph replays
    __threadfence();
    __syncthreads();

    // ---- stage finals: shW = 2-way fold of g_W2, shH = g_H (256 threads) ----
    __shared__ float2 shW[T_DIM * W_DIM];
    __shared__ float2 shH[T_DIM * H_DIM];
    for (int p = tid; p < T_DIM * W_DIM; p += 256) {
        const int t = p / W_DIM;
        const int w = p % W_DIM;
        float2 a = g_W2[(t * 2) * W_DIM + w];
        float2 b = g_W2[(t * 2 + 1) * W_DIM + w];
        shW[p] = make_float2(a.x + b.x, a.y + b.y);
        shH[p] = g_H[p];
    }
    __syncthreads();

    // ---- scans: 64 threads = 32 t x 2 axes ----
    __shared__ float shS[64];
    if (tid < 64) {
        const int t  = tid & 31;
        const int ax = tid >> 5;  // 0 = H, 1 = W
        const float2* __restrict__ s = (ax ? shW : shH) + t * 56;

        const float n_other = (float)(C_DIM) * 56.f;  // 28672
        float total = 0.f;

        float csq = 0.f, clin = 0.f;
        #pragma unroll
        for (int i = 55; i >= 0; --i) {           // suffix slices [i:]
            float2 v = s[i];
            clin += v.x;
            csq  += v.y;
            float n = n_other * (float)(56 - i);
            total += sqrtf(csq + 2.f * EPSF * clin + (EPSF * EPSF) * n) + EPSF;
        }
        csq = 0.f; clin = 0.f;
        #pragma unroll
        for (int i = 0; i < 56; ++i) {            // prefix slices [:j+1]
            float2 v = s[i];
            clin += v.x;
            csq  += v.y;
            float n = n_other * (float)(i + 1);
            total += sqrtf(csq + 2.f * EPSF * clin + (EPSF * EPSF) * n) + EPSF;
        }
        shS[tid] = total;
    }
    __syncthreads();
    if (tid < 32) {
        float v = shS[tid] + shS[tid + 32];
        #pragma unroll
        for (int off = 16; off > 0; off >>= 1)
            v += __shfl_down_sync(0xffffffffu, v, off);
        if (tid == 0) out[0] = v / 128.f;  // / (T=32 * 4 losses)
    }
}

// ---------------------------------------------------------------------------
extern "C" void kernel_launch(void* const* d_in, const int* in_sizes, int n_in,
                              void* d_out, int out_size)
{
    const float* x = (const float*)d_in[0];
    float* out = (float*)d_out;
    (void)in_sizes; (void)n_in; (void)out_size;

    reduce_kernel<<<GRID1, 224>>>(x);
    tail_kernel<<<GRID2, 256>>>(out);
}